// round 15
// baseline (speedup 1.0000x reference)
#include <cuda_runtime.h>
#include <cuda_bf16.h>

// Problem shape (LogRegBaseline): B=64, T=2048, V=512
#define BB    64
#define TT    2048
#define VV    512
#define TM1   (TT - 1)           // 2047 output positions
#define NSEG  16                 // activation-index segments per batch
#define SEG   32                 // activations per segment (== NSUB sub-size)
#define NSUB  16                 // sub-segments for segsum (32 acts each)
#define ZA    16                 // zero slices per batch in setup      (zr/2)
#define ZB    8                  // zero slices per batch in sort       (zr/4)
#define ZC    8                  // zero slices per batch in segsum     (zr/4)
#define FILLG 18                 // S-fill slices per batch (proven fast shape)

// Scratch (device globals; no allocation allowed)
__device__ int   g_ft[BB * VV];          // first-activation time per (b,v); TT if never
__device__ int   g_tlast[BB];            // max activation time per batch (0 if none)
__device__ int   g_alist[BB * VV];       // activation v's sorted by time
__device__ int   g_atime[BB * VV];       // matching sorted times
__device__ int   g_acnt[BB];             // number of activations per batch
__device__ float g_Wt[VV * VV];          // W transposed: Wt[v*VV+u] = W[u*VV+v]
__device__ float g_seg[BB * NSUB * VV];  // per-sub-segment column sums
__device__ float g_S[BB * VV];           // steady row: bias (setup) + atomic sub-sums

// Zero rows [r0, r1) of batch b (128 f4 lanes x nphase row phases)
__device__ __forceinline__ void zero_rows(float* __restrict__ out, int b,
                                          int r0, int r1, int tid, int nphase) {
    const int lane = tid & 127;
    const int ph   = tid >> 7;
    float4* obase = (float4*)out + (size_t)b * TM1 * (VV / 4) + lane;
    const float4 Z = make_float4(0.f, 0.f, 0.f, 0.f);
    for (int t = r0 + ph; t < r1; t += nphase)
        __stcs(&obase[(size_t)t * (VV / 4)], Z);
}

// ---------------------------------------------------------------------------
// Kernel 1 (setup), grid (128 + 256 + 64 + ZA*BB) x 256.  Pole-first order:
//   bid < 128               : first-activation scan   (longest pole)
//   next 256                : W-transpose tiles
//   next 64                 : g_S[b] = bias
//   rest (ZA*BB)            : zero-fill rows [limit, limit+zr/2)
// ---------------------------------------------------------------------------
__global__ void setup(const float* __restrict__ W, const float* __restrict__ codes,
                      const int* __restrict__ lengths, const float* __restrict__ bias,
                      float* __restrict__ out) {
    const int bid = blockIdx.x;
    const int tid = threadIdx.x;

    if (bid < 128) {
        // ---- first-activation scan (early exit at own ft) ----
        const int b = bid >> 1;
        const int v = ((bid & 1) << 8) + tid;
        const float* p = codes + (size_t)b * TT * VV + v;
        int myft = TT;
        for (int t0 = 0; t0 < TT; t0 += 16) {
            float x[16];
#pragma unroll
            for (int k = 0; k < 16; k++) x[k] = p[(size_t)(t0 + k) * VV];
            bool hit = false;
#pragma unroll
            for (int k = 0; k < 16; k++) {
                if (!hit && x[k] != 0.0f) { hit = true; myft = t0 + k; }
            }
            if (hit) break;
        }
        g_ft[b * VV + v] = myft;
        return;
    }

    if (bid < 128 + 256) {
        // ---- transpose W[u,v] -> Wt[v,u] ----
        const int tb = bid - 128;
        __shared__ float tile[32][33];
        const int tx = tid & 31, ty = tid >> 5;        // 32 x 8
        const int bx = tb & 15, by = tb >> 4;
        int x = bx * 32 + tx;
        int y = by * 32 + ty;
#pragma unroll
        for (int j = 0; j < 32; j += 8)
            tile[ty + j][tx] = W[(size_t)(y + j) * VV + x];
        __syncthreads();
        x = by * 32 + tx;
        y = bx * 32 + ty;
#pragma unroll
        for (int j = 0; j < 32; j += 8)
            g_Wt[(size_t)(y + j) * VV + x] = tile[tx][ty + j];
        return;
    }

    if (bid < 128 + 256 + 64) {
        // ---- init g_S[b] = bias ----
        const int b = bid - 128 - 256;
        g_S[b * VV + tid]       = bias[tid];
        g_S[b * VV + 256 + tid] = bias[256 + tid];
        return;
    }

    // ---- zero-fill rows [limit, limit+zr/2) ----
    const int z     = bid - 128 - 256 - 64;
    const int b     = z / ZA;
    const int slice = z % ZA;
    const int limit = lengths[b] - 1;
    const int zr    = TM1 - limit;
    const int z0    = limit;
    const int z1    = limit + zr / 2;
    const int span  = z1 - z0;
    if (span <= 0) return;
    const int per = (span + ZA - 1) / ZA;
    const int r0  = z0 + slice * per;
    const int r1  = min(r0 + per, z1);
    if (r0 < r1) zero_rows(out, b, r0, r1, tid, 2);
}

// ---------------------------------------------------------------------------
// Kernel 2 (sort + zero), grid (BB + ZB*BB) x 512.  Sort (pole) first:
//   bid < BB  : per-batch counting sort + t_last (warp-shuffle scans)
//   else      : zero-fill rows [limit+zr/2, limit+3zr/4)
// ---------------------------------------------------------------------------
__global__ void sort_acts(const int* __restrict__ lengths, float* __restrict__ out) {
    const int bid = blockIdx.x;
    const int tid = threadIdx.x;

    if (bid >= BB) {
        const int z     = bid - BB;
        const int b     = z / ZB;
        const int slice = z % ZB;
        const int limit = lengths[b] - 1;
        const int zr    = TM1 - limit;
        const int z0    = limit + zr / 2;
        const int z1    = limit + (3 * zr) / 4;
        const int span  = z1 - z0;
        if (span <= 0) return;
        const int per = (span + ZB - 1) / ZB;
        const int r0  = z0 + slice * per;
        const int r1  = min(r0 + per, z1);
        if (r0 < r1) zero_rows(out, b, r0, r1, tid, 4);
        return;
    }

    const int b    = bid;
    const int warp = tid >> 5, lane = tid & 31;
    __shared__ int cnt[TT];
    __shared__ int wred[16];

    const int myft = g_ft[b * VV + tid];

    // t_last
    int m = (myft < TT) ? myft : 0;
#pragma unroll
    for (int off = 16; off; off >>= 1) m = max(m, __shfl_xor_sync(0xffffffffu, m, off));
    if (lane == 0) wred[warp] = m;
    __syncthreads();
    if (tid == 0) {
        int mm = 0;
#pragma unroll
        for (int i = 0; i < 16; i++) mm = max(mm, wred[i]);
        g_tlast[b] = mm;
    }
    __syncthreads();

#pragma unroll
    for (int k = 0; k < 4; k++) cnt[k * VV + tid] = 0;
    __syncthreads();
    if (myft < TT) atomicAdd(&cnt[myft], 1);
    __syncthreads();

    const int a0 = cnt[4 * tid], a1 = cnt[4 * tid + 1];
    const int a2 = cnt[4 * tid + 2], a3 = cnt[4 * tid + 3];
    const int mysum = a0 + a1 + a2 + a3;
    int inc = mysum;
#pragma unroll
    for (int d = 1; d < 32; d <<= 1) {
        int t = __shfl_up_sync(0xffffffffu, inc, d);
        if (lane >= d) inc += t;
    }
    if (lane == 31) wred[warp] = inc;
    __syncthreads();
    if (warp == 0 && lane < 16) {
        int v = wred[lane];
#pragma unroll
        for (int d = 1; d < 16; d <<= 1) {
            int t = __shfl_up_sync(0x0000ffffu, v, d);
            if (lane >= d) v += t;
        }
        wred[lane] = v;
    }
    __syncthreads();
    const int wbase = (warp > 0) ? wred[warp - 1] : 0;
    const int ex    = wbase + inc - mysum;
    cnt[4 * tid]     = ex;
    cnt[4 * tid + 1] = ex + a0;
    cnt[4 * tid + 2] = ex + a0 + a1;
    cnt[4 * tid + 3] = ex + a0 + a1 + a2;
    if (tid == VV - 1) g_acnt[b] = wbase + inc;
    __syncthreads();

    if (myft < TT) {
        int pos = atomicAdd(&cnt[myft], 1);
        g_alist[b * VV + pos] = tid;
        g_atime[b * VV + pos] = myft;
    }
}

// ---------------------------------------------------------------------------
// Kernel 3 (segsum + zero), grid (NSUB*BB + ZC*BB) x 512.  Segsum first:
//   bid < NSUB*BB : per-sub-segment column sums; atomicAdd into g_S
//   else          : zero-fill rows [limit+3zr/4, TM1)
// ---------------------------------------------------------------------------
__global__ void segsum(const int* __restrict__ lengths, float* __restrict__ out) {
    const int bid = blockIdx.x;
    const int tid = threadIdx.x;

    if (bid >= NSUB * BB) {
        const int z     = bid - NSUB * BB;
        const int b     = z / ZC;
        const int slice = z % ZC;
        const int limit = lengths[b] - 1;
        const int zr    = TM1 - limit;
        const int z0    = limit + (3 * zr) / 4;
        const int z1    = TM1;
        const int span  = z1 - z0;
        if (span <= 0) return;
        const int per = (span + ZC - 1) / ZC;
        const int r0  = z0 + slice * per;
        const int r1  = min(r0 + per, z1);
        if (r0 < r1) zero_rows(out, b, r0, r1, tid, 4);
        return;
    }

    const int sub = bid % NSUB;
    const int b   = bid / NSUB;
    const int u   = tid;
    __shared__ int sl[32];

    const int A  = g_acnt[b];
    const int i0 = sub * 32;
    const int i1 = min(i0 + 32, A);
    const int n  = max(i1 - i0, 0);

    if (u < 32 && u < n) sl[u] = g_alist[b * VV + i0 + u];
    __syncthreads();

    float acc = 0.0f;
    int i = 0;
    for (; i + 8 <= n; i += 8) {
        float w0 = g_Wt[sl[i + 0] * VV + u];
        float w1 = g_Wt[sl[i + 1] * VV + u];
        float w2 = g_Wt[sl[i + 2] * VV + u];
        float w3 = g_Wt[sl[i + 3] * VV + u];
        float w4 = g_Wt[sl[i + 4] * VV + u];
        float w5 = g_Wt[sl[i + 5] * VV + u];
        float w6 = g_Wt[sl[i + 6] * VV + u];
        float w7 = g_Wt[sl[i + 7] * VV + u];
        acc += ((w0 + w1) + (w2 + w3)) + ((w4 + w5) + (w6 + w7));
    }
    for (; i < n; i++) acc += g_Wt[sl[i] * VV + u];

    g_seg[((size_t)b * NSUB + sub) * VV + u] = acc;
    if (n > 0) atomicAdd(&g_S[b * VV + u], acc);
}

// ---------------------------------------------------------------------------
// Kernel 4 (varying only), grid (NSEG, BB) x 128:
// segment s = sorted activation indices [32s, 32s+32); rows between act times.
// Start state: UNROLLED predicated loads (15-way MLP instead of serial chain).
// Depth-8 register prefetch (no launch_bounds -> no spill).
// ---------------------------------------------------------------------------
__global__ void varying_k(const int* __restrict__ lengths, const float* __restrict__ bias,
                          float* __restrict__ out) {
    const int s     = blockIdx.x;
    const int b     = blockIdx.y;
    const int tid   = threadIdx.x;          // float4 lane
    const int limit = lengths[b] - 1;
    const int vend  = min(g_tlast[b], limit);
    if (vend <= 0) return;

    const int A  = g_acnt[b];
    const int i0 = s * SEG;
    const int i1 = min(i0 + SEG, A);
    const int n  = max(i1 - i0, 0);
    if (s > 0 && n == 0) return;

    __shared__ int sl[SEG];
    __shared__ int st[SEG];
    __shared__ int s_end;
    if (tid < n) {
        sl[tid] = g_alist[b * VV + i0 + tid];
        st[tid] = g_atime[b * VV + i0 + tid];
    }
    if (tid == 0) s_end = (i1 < A) ? g_atime[b * VV + i1] : vend;
    __syncthreads();

    const int ts = (s == 0) ? 0 : ((n > 0) ? st[0] : vend);
    const int ve = min(s_end, vend);
    if (ts >= ve) return;

    float4* obase = (float4*)out + (size_t)b * TM1 * (VV / 4) + tid;

    // Starting state = bias + ordered sub-sums [0, s).
    // UNROLLED + predicated: all <=15 loads issue independently (MLP),
    // FADD chain drains after one L2 round-trip instead of 15.
    const float4* seg4 = (const float4*)(g_seg + (size_t)b * NSUB * VV);
    float4 L = ((const float4*)bias)[tid];
#pragma unroll
    for (int q = 0; q < NSUB - 1; q++) {
        if (q < s) {
            float4 g = seg4[q * (VV / 4) + tid];
            L.x += g.x; L.y += g.y; L.z += g.z; L.w += g.w;
        }
    }

    // Static 8-deep register prefetch over Wt columns
    float4 w[8];
#pragma unroll
    for (int k = 0; k < 8; k++)
        w[k] = (k < n) ? ((const float4*)(g_Wt + (size_t)sl[k] * VV))[tid]
                       : make_float4(0.f, 0.f, 0.f, 0.f);

    int wt = ts;
    for (int base = 0; base < n; base += 8) {
#pragma unroll
        for (int k = 0; k < 8; k++) {
            const int i = base + k;
            if (i < n) {
                const int te = min(st[i], ve);
                while (wt < te) { __stcs(&obase[(size_t)wt * (VV / 4)], L); wt++; }
                L.x += w[k].x; L.y += w[k].y; L.z += w[k].z; L.w += w[k].w;
                const int j = i + 8;
                if (j < n)
                    w[k] = ((const float4*)(g_Wt + (size_t)sl[j] * VV))[tid];
            }
        }
    }
    while (wt < ve) { __stcs(&obase[(size_t)wt * (VV / 4)], L); wt++; }
}

// ---------------------------------------------------------------------------
// Kernel 5 (pure S-fill, proven-fast shape), grid (FILLG, BB) x 512:
// rows [vend, limit) get the steady row S_b. Homogeneous streaming stores.
// ---------------------------------------------------------------------------
__global__ void __launch_bounds__(512)
fill_k(const int* __restrict__ lengths, float* __restrict__ out) {
    const int b     = blockIdx.y;
    const int limit = lengths[b] - 1;
    const int vend  = min(g_tlast[b], limit);

    const int total = limit - vend;
    if (total <= 0) return;
    const int per = (total + FILLG - 1) / FILLG;
    const int r0  = vend + blockIdx.x * per;
    const int r1  = min(r0 + per, limit);
    if (r0 >= r1) return;

    const int lane = threadIdx.x & 127;
    const int sub  = threadIdx.x >> 7;     // 0..3 row phases

    const float4 S = ((const float4*)(g_S + (size_t)b * VV))[lane];
    float4* obase = (float4*)out + (size_t)b * TM1 * (VV / 4) + lane;

    int t = r0 + sub;
#pragma unroll 8
    for (; t < r1; t += 4)
        __stcs(&obase[(size_t)t * (VV / 4)], S);
}

// ---------------------------------------------------------------------------
// Launch. Inputs (metadata order): times[B,T] f32, codes[B,T,V] f32,
// lengths[B] i32, W[V,V] f32, b[V] f32. Output: [B, T-1, V] f32.
// ---------------------------------------------------------------------------
extern "C" void kernel_launch(void* const* d_in, const int* in_sizes, int n_in,
                              void* d_out, int out_size) {
    const float* codes   = (const float*)d_in[1];
    const int*   lengths = (const int*)d_in[2];
    const float* W       = (const float*)d_in[3];
    const float* bias    = (const float*)d_in[4];
    float*       out     = (float*)d_out;

    setup<<<128 + 256 + 64 + ZA * BB, 256>>>(W, codes, lengths, bias, out);
    sort_acts<<<BB + ZB * BB, 512>>>(lengths, out);
    segsum<<<NSUB * BB + ZC * BB, 512>>>(lengths, out);
    varying_k<<<dim3(NSEG, BB), 128>>>(lengths, bias, out);
    fill_k<<<dim3(FILLG, BB), 512>>>(lengths, out);
}

// round 16
// speedup vs baseline: 1.0298x; 1.0298x over previous
#include <cuda_runtime.h>
#include <cuda_bf16.h>

// Problem shape (LogRegBaseline): B=64, T=2048, V=512
#define BB    64
#define TT    2048
#define VV    512
#define TM1   (TT - 1)           // 2047 output positions
#define NSEG  8                  // varying segments per batch (512 CTAs total)
#define SEG   64                 // activations per varying segment
#define NSUB  16                 // sub-segments for segsum (32 acts each)
#define ZA    16                 // zero slices/batch in setup   [0, zr/2)
#define ZSORT 4                  // zero slices/batch in sort    [zr/2, 5zr/8)
#define ZSEG  4                  // zero slices/batch in segsum  [5zr/8, 3zr/4)
#define ZV    4                  // zero slices/batch in mega    [3zr/4, zr)
#define FILLG 12                 // fill slices/batch in mega    [vend, limit)

// Scratch (device globals; no allocation allowed)
__device__ int   g_ft[BB * VV];          // first-activation time per (b,v); TT if never
__device__ int   g_tlast[BB];            // max activation time per batch (0 if none)
__device__ int   g_alist[BB * VV];       // activation v's sorted by time
__device__ int   g_atime[BB * VV];       // matching sorted times
__device__ int   g_acnt[BB];             // number of activations per batch
__device__ float g_Wt[VV * VV];          // W transposed: Wt[v*VV+u] = W[u*VV+v]
__device__ float g_seg[BB * NSUB * VV];  // per-sub-segment column sums
__device__ float g_S[BB * VV];           // steady row: bias (setup) + atomic sub-sums

// Zero rows [r0, r1) of batch b (128 f4 lanes x nphase row phases)
__device__ __forceinline__ void zero_rows(float* __restrict__ out, int b,
                                          int r0, int r1, int tid, int nphase) {
    const int lane = tid & 127;
    const int ph   = tid >> 7;
    float4* obase = (float4*)out + (size_t)b * TM1 * (VV / 4) + lane;
    const float4 Z = make_float4(0.f, 0.f, 0.f, 0.f);
    for (int t = r0 + ph; t < r1; t += nphase)
        __stcs(&obase[(size_t)t * (VV / 4)], Z);
}

// ---------------------------------------------------------------------------
// Kernel 1 (setup), grid (128 + 256 + 64 + ZA*BB) x 256.  Pole-first order:
//   bid < 128 : first-activation scan (longest pole)
//   next 256  : W-transpose tiles
//   next 64   : g_S[b] = bias
//   rest      : zero-fill rows [limit, limit + zr/2)
// ---------------------------------------------------------------------------
__global__ void setup(const float* __restrict__ W, const float* __restrict__ codes,
                      const int* __restrict__ lengths, const float* __restrict__ bias,
                      float* __restrict__ out) {
    const int bid = blockIdx.x;
    const int tid = threadIdx.x;

    if (bid < 128) {
        const int b = bid >> 1;
        const int v = ((bid & 1) << 8) + tid;
        const float* p = codes + (size_t)b * TT * VV + v;
        int myft = TT;
        for (int t0 = 0; t0 < TT; t0 += 16) {
            float x[16];
#pragma unroll
            for (int k = 0; k < 16; k++) x[k] = p[(size_t)(t0 + k) * VV];
            bool hit = false;
#pragma unroll
            for (int k = 0; k < 16; k++) {
                if (!hit && x[k] != 0.0f) { hit = true; myft = t0 + k; }
            }
            if (hit) break;
        }
        g_ft[b * VV + v] = myft;
        return;
    }

    if (bid < 128 + 256) {
        const int tb = bid - 128;
        __shared__ float tile[32][33];
        const int tx = tid & 31, ty = tid >> 5;        // 32 x 8
        const int bx = tb & 15, by = tb >> 4;
        int x = bx * 32 + tx;
        int y = by * 32 + ty;
#pragma unroll
        for (int j = 0; j < 32; j += 8)
            tile[ty + j][tx] = W[(size_t)(y + j) * VV + x];
        __syncthreads();
        x = by * 32 + tx;
        y = bx * 32 + ty;
#pragma unroll
        for (int j = 0; j < 32; j += 8)
            g_Wt[(size_t)(y + j) * VV + x] = tile[tx][ty + j];
        return;
    }

    if (bid < 128 + 256 + 64) {
        const int b = bid - 128 - 256;
        g_S[b * VV + tid]       = bias[tid];
        g_S[b * VV + 256 + tid] = bias[256 + tid];
        return;
    }

    const int z     = bid - 128 - 256 - 64;
    const int b     = z / ZA;
    const int slice = z % ZA;
    const int limit = lengths[b] - 1;
    const int zr    = TM1 - limit;
    const int z0    = limit;
    const int z1    = limit + zr / 2;
    const int span  = z1 - z0;
    if (span <= 0) return;
    const int per = (span + ZA - 1) / ZA;
    const int r0  = z0 + slice * per;
    const int r1  = min(r0 + per, z1);
    if (r0 < r1) zero_rows(out, b, r0, r1, tid, 2);
}

// ---------------------------------------------------------------------------
// Kernel 2 (sort + small zero), grid (BB + ZSORT*BB) x 512.  Sort first:
//   bid < BB : per-batch counting sort + t_last (warp-shuffle scans)
//   else     : zero-fill rows [limit + zr/2, limit + 5zr/8)
// ---------------------------------------------------------------------------
__global__ void sort_acts(const int* __restrict__ lengths, float* __restrict__ out) {
    const int bid = blockIdx.x;
    const int tid = threadIdx.x;

    if (bid >= BB) {
        const int z     = bid - BB;
        const int b     = z / ZSORT;
        const int slice = z % ZSORT;
        const int limit = lengths[b] - 1;
        const int zr    = TM1 - limit;
        const int z0    = limit + zr / 2;
        const int z1    = limit + (5 * zr) / 8;
        const int span  = z1 - z0;
        if (span <= 0) return;
        const int per = (span + ZSORT - 1) / ZSORT;
        const int r0  = z0 + slice * per;
        const int r1  = min(r0 + per, z1);
        if (r0 < r1) zero_rows(out, b, r0, r1, tid, 4);
        return;
    }

    const int b    = bid;
    const int warp = tid >> 5, lane = tid & 31;
    __shared__ int cnt[TT];
    __shared__ int wred[16];

    const int myft = g_ft[b * VV + tid];

    int m = (myft < TT) ? myft : 0;
#pragma unroll
    for (int off = 16; off; off >>= 1) m = max(m, __shfl_xor_sync(0xffffffffu, m, off));
    if (lane == 0) wred[warp] = m;
    __syncthreads();
    if (tid == 0) {
        int mm = 0;
#pragma unroll
        for (int i = 0; i < 16; i++) mm = max(mm, wred[i]);
        g_tlast[b] = mm;
    }
    __syncthreads();

#pragma unroll
    for (int k = 0; k < 4; k++) cnt[k * VV + tid] = 0;
    __syncthreads();
    if (myft < TT) atomicAdd(&cnt[myft], 1);
    __syncthreads();

    const int a0 = cnt[4 * tid], a1 = cnt[4 * tid + 1];
    const int a2 = cnt[4 * tid + 2], a3 = cnt[4 * tid + 3];
    const int mysum = a0 + a1 + a2 + a3;
    int inc = mysum;
#pragma unroll
    for (int d = 1; d < 32; d <<= 1) {
        int t = __shfl_up_sync(0xffffffffu, inc, d);
        if (lane >= d) inc += t;
    }
    if (lane == 31) wred[warp] = inc;
    __syncthreads();
    if (warp == 0 && lane < 16) {
        int v = wred[lane];
#pragma unroll
        for (int d = 1; d < 16; d <<= 1) {
            int t = __shfl_up_sync(0x0000ffffu, v, d);
            if (lane >= d) v += t;
        }
        wred[lane] = v;
    }
    __syncthreads();
    const int wbase = (warp > 0) ? wred[warp - 1] : 0;
    const int ex    = wbase + inc - mysum;
    cnt[4 * tid]     = ex;
    cnt[4 * tid + 1] = ex + a0;
    cnt[4 * tid + 2] = ex + a0 + a1;
    cnt[4 * tid + 3] = ex + a0 + a1 + a2;
    if (tid == VV - 1) g_acnt[b] = wbase + inc;
    __syncthreads();

    if (myft < TT) {
        int pos = atomicAdd(&cnt[myft], 1);
        g_alist[b * VV + pos] = tid;
        g_atime[b * VV + pos] = myft;
    }
}

// ---------------------------------------------------------------------------
// Kernel 3 (segsum + small zero), grid (NSUB*BB + ZSEG*BB) x 512.  Segsum first:
//   bid < NSUB*BB : per-sub-segment column sums; atomicAdd into g_S
//   else          : zero-fill rows [limit + 5zr/8, limit + 3zr/4)
// ---------------------------------------------------------------------------
__global__ void segsum(const int* __restrict__ lengths, float* __restrict__ out) {
    const int bid = blockIdx.x;
    const int tid = threadIdx.x;

    if (bid >= NSUB * BB) {
        const int z     = bid - NSUB * BB;
        const int b     = z / ZSEG;
        const int slice = z % ZSEG;
        const int limit = lengths[b] - 1;
        const int zr    = TM1 - limit;
        const int z0    = limit + (5 * zr) / 8;
        const int z1    = limit + (3 * zr) / 4;
        const int span  = z1 - z0;
        if (span <= 0) return;
        const int per = (span + ZSEG - 1) / ZSEG;
        const int r0  = z0 + slice * per;
        const int r1  = min(r0 + per, z1);
        if (r0 < r1) zero_rows(out, b, r0, r1, tid, 4);
        return;
    }

    const int sub = bid % NSUB;
    const int b   = bid / NSUB;
    const int u   = tid;
    __shared__ int sl[32];

    const int A  = g_acnt[b];
    const int i0 = sub * 32;
    const int i1 = min(i0 + 32, A);
    const int n  = max(i1 - i0, 0);

    if (u < 32 && u < n) sl[u] = g_alist[b * VV + i0 + u];
    __syncthreads();

    float acc = 0.0f;
    int i = 0;
    for (; i + 8 <= n; i += 8) {
        float w0 = g_Wt[sl[i + 0] * VV + u];
        float w1 = g_Wt[sl[i + 1] * VV + u];
        float w2 = g_Wt[sl[i + 2] * VV + u];
        float w3 = g_Wt[sl[i + 3] * VV + u];
        float w4 = g_Wt[sl[i + 4] * VV + u];
        float w5 = g_Wt[sl[i + 5] * VV + u];
        float w6 = g_Wt[sl[i + 6] * VV + u];
        float w7 = g_Wt[sl[i + 7] * VV + u];
        acc += ((w0 + w1) + (w2 + w3)) + ((w4 + w5) + (w6 + w7));
    }
    for (; i < n; i++) acc += g_Wt[sl[i] * VV + u];

    g_seg[((size_t)b * NSUB + sub) * VV + u] = acc;
    if (n > 0) atomicAdd(&g_S[b * VV + u], acc);
}

// ---------------------------------------------------------------------------
// Kernel 4 (MEGA output), grid (NSEG*BB + FILLG*BB + ZV*BB) x 128:
//   bid < NSEG*BB            : varying segment (38% of slots; launches first)
//   next FILLG*BB            : S-fill slice over [vend, limit)
//   last ZV*BB               : zero slice over [limit + 3zr/4, TM1)
// Store CTAs co-reside with stalled varying CTAs and stream DRAM meanwhile.
// ---------------------------------------------------------------------------
__global__ void output_k(const int* __restrict__ lengths, const float* __restrict__ bias,
                         float* __restrict__ out) {
    const int bid = blockIdx.x;
    const int tid = threadIdx.x;           // float4 lane

    if (bid < NSEG * BB) {
        // ---- varying segment (SEG=64 acts) ----
        const int b     = bid / NSEG;
        const int s     = bid % NSEG;
        const int limit = lengths[b] - 1;
        const int vend  = min(g_tlast[b], limit);
        if (vend <= 0) return;

        const int A  = g_acnt[b];
        const int i0 = s * SEG;
        const int i1 = min(i0 + SEG, A);
        const int n  = max(i1 - i0, 0);
        if (s > 0 && n == 0) return;

        __shared__ int sl[SEG];
        __shared__ int st[SEG];
        __shared__ int s_end;
        if (tid < n) {
            sl[tid] = g_alist[b * VV + i0 + tid];
            st[tid] = g_atime[b * VV + i0 + tid];
        }
        if (tid == 0) s_end = (i1 < A) ? g_atime[b * VV + i1] : vend;
        __syncthreads();

        const int ts = (s == 0) ? 0 : ((n > 0) ? st[0] : vend);
        const int ve = min(s_end, vend);
        if (ts >= ve) return;

        float4* obase = (float4*)out + (size_t)b * TM1 * (VV / 4) + tid;

        // Start state = bias + ordered sub-sums [0, 2s), unrolled + predicated (MLP)
        const float4* seg4 = (const float4*)(g_seg + (size_t)b * NSUB * VV);
        float4 L = ((const float4*)bias)[tid];
#pragma unroll
        for (int q = 0; q < 2 * (NSEG - 1); q++) {
            if (q < 2 * s) {
                float4 g = seg4[q * (VV / 4) + tid];
                L.x += g.x; L.y += g.y; L.z += g.z; L.w += g.w;
            }
        }

        // Static 8-deep register prefetch over Wt columns
        float4 w[8];
#pragma unroll
        for (int k = 0; k < 8; k++)
            w[k] = (k < n) ? ((const float4*)(g_Wt + (size_t)sl[k] * VV))[tid]
                           : make_float4(0.f, 0.f, 0.f, 0.f);

        int wt = ts;
        for (int base = 0; base < n; base += 8) {
#pragma unroll
            for (int k = 0; k < 8; k++) {
                const int i = base + k;
                if (i < n) {
                    const int te = min(st[i], ve);
                    while (wt < te) { __stcs(&obase[(size_t)wt * (VV / 4)], L); wt++; }
                    L.x += w[k].x; L.y += w[k].y; L.z += w[k].z; L.w += w[k].w;
                    const int j = i + 8;
                    if (j < n)
                        w[k] = ((const float4*)(g_Wt + (size_t)sl[j] * VV))[tid];
                }
            }
        }
        while (wt < ve) { __stcs(&obase[(size_t)wt * (VV / 4)], L); wt++; }
        return;
    }

    // ---- store CTAs: fill (value S) or zero-tail (value 0) ----
    int b, r0, r1;
    float4 val;

    if (bid < NSEG * BB + FILLG * BB) {
        const int f     = bid - NSEG * BB;
        b               = f / FILLG;
        const int slice = f % FILLG;
        const int limit = lengths[b] - 1;
        const int vend  = min(g_tlast[b], limit);
        const int total = limit - vend;
        if (total <= 0) return;
        const int per = (total + FILLG - 1) / FILLG;
        r0 = vend + slice * per;
        r1 = min(r0 + per, limit);
        if (r0 >= r1) return;
        val = ((const float4*)(g_S + (size_t)b * VV))[tid];
    } else {
        const int z     = bid - NSEG * BB - FILLG * BB;
        b               = z / ZV;
        const int slice = z % ZV;
        const int limit = lengths[b] - 1;
        const int zr    = TM1 - limit;
        const int z0    = limit + (3 * zr) / 4;
        const int span  = TM1 - z0;
        if (span <= 0) return;
        const int per = (span + ZV - 1) / ZV;
        r0 = z0 + slice * per;
        r1 = min(r0 + per, TM1);
        if (r0 >= r1) return;
        val = make_float4(0.f, 0.f, 0.f, 0.f);
    }

    float4* obase = (float4*)out + (size_t)b * TM1 * (VV / 4) + tid;
#pragma unroll 8
    for (int t = r0; t < r1; t++)
        __stcs(&obase[(size_t)t * (VV / 4)], val);
}

// ---------------------------------------------------------------------------
// Launch. Inputs (metadata order): times[B,T] f32, codes[B,T,V] f32,
// lengths[B] i32, W[V,V] f32, b[V] f32. Output: [B, T-1, V] f32.
// ---------------------------------------------------------------------------
extern "C" void kernel_launch(void* const* d_in, const int* in_sizes, int n_in,
                              void* d_out, int out_size) {
    const float* codes   = (const float*)d_in[1];
    const int*   lengths = (const int*)d_in[2];
    const float* W       = (const float*)d_in[3];
    const float* bias    = (const float*)d_in[4];
    float*       out     = (float*)d_out;

    setup<<<128 + 256 + 64 + ZA * BB, 256>>>(W, codes, lengths, bias, out);
    sort_acts<<<BB + ZSORT * BB, 512>>>(lengths, out);
    segsum<<<NSUB * BB + ZSEG * BB, 512>>>(lengths, out);
    output_k<<<NSEG * BB + FILLG * BB + ZV * BB, 128>>>(lengths, bias, out);
}

// round 17
// speedup vs baseline: 1.0844x; 1.0530x over previous
#include <cuda_runtime.h>
#include <cuda_bf16.h>

// Problem shape (LogRegBaseline): B=64, T=2048, V=512
#define BB    64
#define TT    2048
#define VV    512
#define TM1   (TT - 1)           // 2047 output positions
#define NSEG  8                  // activation-index segments per batch (output view)
#define SEG   64                 // activations per segment
#define NSUB  16                 // sub-segments for segsum (32 acts each)
#define FILLG 64                 // S-fill slices per batch (output kernel)
#define ZA    16                 // zero slices per batch in setup      (zr/2)
#define ZB    8                  // zero slices per batch in sort       (zr/4)
#define ZC    8                  // zero slices per batch in segsum     (zr/4)

// Scratch (device globals; no allocation allowed)
__device__ int   g_ft[BB * VV];          // first-activation time per (b,v); TT if never
__device__ int   g_tlast[BB];            // max activation time per batch (0 if none)
__device__ int   g_alist[BB * VV];       // activation v's sorted by time
__device__ int   g_atime[BB * VV];       // matching sorted times
__device__ int   g_acnt[BB];             // number of activations per batch
__device__ float g_Wt[VV * VV];          // W transposed: Wt[v*VV+u] = W[u*VV+v]
__device__ float g_seg[BB * NSUB * VV];  // per-sub-segment column sums
__device__ float g_S[BB * VV];           // steady row: bias (setup) + atomic sub-sums

// Zero-fill rows [r0, r1) of batch b (128 f4 lanes x nphase row phases)
__device__ __forceinline__ void zero_rows(float* __restrict__ out, int b,
                                          int r0, int r1, int tid, int nphase) {
    const int lane = tid & 127;
    const int ph   = tid >> 7;
    float4* obase = (float4*)out + (size_t)b * TM1 * (VV / 4) + lane;
    const float4 Z = make_float4(0.f, 0.f, 0.f, 0.f);
    for (int t = r0 + ph; t < r1; t += nphase)
        __stcs(&obase[(size_t)t * (VV / 4)], Z);
}

// ---------------------------------------------------------------------------
// Kernel 1 (setup), grid (ZA*BB + 256 + 128 + 64) x 256:
//   bid < ZA*BB             : zero-fill rows [limit, limit+zr/2)
//   next 256                : W-transpose tiles
//   next 128                : first-activation scan
//   last 64                 : g_S[b] = bias
// ---------------------------------------------------------------------------
__global__ void setup(const float* __restrict__ W, const float* __restrict__ codes,
                      const int* __restrict__ lengths, const float* __restrict__ bias,
                      float* __restrict__ out) {
    const int bid = blockIdx.x;
    const int tid = threadIdx.x;

    if (bid < ZA * BB) {
        const int b     = bid / ZA;
        const int slice = bid % ZA;
        const int limit = lengths[b] - 1;
        const int zr    = TM1 - limit;
        const int z0    = limit;
        const int z1    = limit + zr / 2;
        const int span  = z1 - z0;
        if (span <= 0) return;
        const int per = (span + ZA - 1) / ZA;
        const int r0  = z0 + slice * per;
        const int r1  = min(r0 + per, z1);
        if (r0 < r1) zero_rows(out, b, r0, r1, tid, 2);
        return;
    }

    if (bid < ZA * BB + 256) {
        // ---- transpose W[u,v] -> Wt[v,u] ----
        const int tb = bid - ZA * BB;
        __shared__ float tile[32][33];
        const int tx = tid & 31, ty = tid >> 5;        // 32 x 8
        const int bx = tb & 15, by = tb >> 4;
        int x = bx * 32 + tx;
        int y = by * 32 + ty;
#pragma unroll
        for (int j = 0; j < 32; j += 8)
            tile[ty + j][tx] = W[(size_t)(y + j) * VV + x];
        __syncthreads();
        x = by * 32 + tx;
        y = bx * 32 + ty;
#pragma unroll
        for (int j = 0; j < 32; j += 8)
            g_Wt[(size_t)(y + j) * VV + x] = tile[tx][ty + j];
        return;
    }

    if (bid < ZA * BB + 256 + 128) {
        // ---- first-activation scan (early exit at own ft) ----
        const int idx = bid - ZA * BB - 256;   // 0..127
        const int b   = idx >> 1;
        const int v   = ((idx & 1) << 8) + tid;
        const float* p = codes + (size_t)b * TT * VV + v;
        int myft = TT;
        for (int t0 = 0; t0 < TT; t0 += 16) {
            float x[16];
#pragma unroll
            for (int k = 0; k < 16; k++) x[k] = p[(size_t)(t0 + k) * VV];
            bool hit = false;
#pragma unroll
            for (int k = 0; k < 16; k++) {
                if (!hit && x[k] != 0.0f) { hit = true; myft = t0 + k; }
            }
            if (hit) break;
        }
        g_ft[b * VV + v] = myft;
        return;
    }

    // ---- init g_S[b] = bias ----
    const int b = bid - ZA * BB - 256 - 128;
    g_S[b * VV + tid]       = bias[tid];
    g_S[b * VV + 256 + tid] = bias[256 + tid];
}

// ---------------------------------------------------------------------------
// Kernel 2 (sort + zero), grid (ZB*BB + BB) x 512:
//   bid < ZB*BB : zero-fill rows [limit+zr/2, limit+3zr/4)
//   else        : per-batch counting sort + t_last (warp-shuffle scans)
// ---------------------------------------------------------------------------
__global__ void sort_acts(const int* __restrict__ lengths, float* __restrict__ out) {
    const int bid = blockIdx.x;
    const int tid = threadIdx.x;

    if (bid < ZB * BB) {
        const int b     = bid / ZB;
        const int slice = bid % ZB;
        const int limit = lengths[b] - 1;
        const int zr    = TM1 - limit;
        const int z0    = limit + zr / 2;
        const int z1    = limit + (3 * zr) / 4;
        const int span  = z1 - z0;
        if (span <= 0) return;
        const int per = (span + ZB - 1) / ZB;
        const int r0  = z0 + slice * per;
        const int r1  = min(r0 + per, z1);
        if (r0 < r1) zero_rows(out, b, r0, r1, tid, 4);
        return;
    }

    const int b    = bid - ZB * BB;
    const int warp = tid >> 5, lane = tid & 31;
    __shared__ int cnt[TT];
    __shared__ int wred[16];

    const int myft = g_ft[b * VV + tid];

    // t_last
    int m = (myft < TT) ? myft : 0;
#pragma unroll
    for (int off = 16; off; off >>= 1) m = max(m, __shfl_xor_sync(0xffffffffu, m, off));
    if (lane == 0) wred[warp] = m;
    __syncthreads();
    if (tid == 0) {
        int mm = 0;
#pragma unroll
        for (int i = 0; i < 16; i++) mm = max(mm, wred[i]);
        g_tlast[b] = mm;
    }
    __syncthreads();

#pragma unroll
    for (int k = 0; k < 4; k++) cnt[k * VV + tid] = 0;
    __syncthreads();
    if (myft < TT) atomicAdd(&cnt[myft], 1);
    __syncthreads();

    const int a0 = cnt[4 * tid], a1 = cnt[4 * tid + 1];
    const int a2 = cnt[4 * tid + 2], a3 = cnt[4 * tid + 3];
    const int mysum = a0 + a1 + a2 + a3;
    int inc = mysum;
#pragma unroll
    for (int d = 1; d < 32; d <<= 1) {
        int t = __shfl_up_sync(0xffffffffu, inc, d);
        if (lane >= d) inc += t;
    }
    if (lane == 31) wred[warp] = inc;
    __syncthreads();
    if (warp == 0 && lane < 16) {
        int v = wred[lane];
#pragma unroll
        for (int d = 1; d < 16; d <<= 1) {
            int t = __shfl_up_sync(0x0000ffffu, v, d);
            if (lane >= d) v += t;
        }
        wred[lane] = v;
    }
    __syncthreads();
    const int wbase = (warp > 0) ? wred[warp - 1] : 0;
    const int ex    = wbase + inc - mysum;
    cnt[4 * tid]     = ex;
    cnt[4 * tid + 1] = ex + a0;
    cnt[4 * tid + 2] = ex + a0 + a1;
    cnt[4 * tid + 3] = ex + a0 + a1 + a2;
    if (tid == VV - 1) g_acnt[b] = wbase + inc;
    __syncthreads();

    if (myft < TT) {
        int pos = atomicAdd(&cnt[myft], 1);
        g_alist[b * VV + pos] = tid;
        g_atime[b * VV + pos] = myft;
    }
}

// ---------------------------------------------------------------------------
// Kernel 3 (segsum + zero), grid (ZC*BB + NSUB*BB) x 512:
//   bid < ZC*BB : zero-fill rows [limit+3zr/4, TM1)
//   else        : per-sub-segment column sums; atomicAdd into g_S
// ---------------------------------------------------------------------------
__global__ void segsum(const int* __restrict__ lengths, float* __restrict__ out) {
    const int bid = blockIdx.x;
    const int tid = threadIdx.x;

    if (bid < ZC * BB) {
        const int b     = bid / ZC;
        const int slice = bid % ZC;
        const int limit = lengths[b] - 1;
        const int zr    = TM1 - limit;
        const int z0    = limit + (3 * zr) / 4;
        const int z1    = TM1;
        const int span  = z1 - z0;
        if (span <= 0) return;
        const int per = (span + ZC - 1) / ZC;
        const int r0  = z0 + slice * per;
        const int r1  = min(r0 + per, z1);
        if (r0 < r1) zero_rows(out, b, r0, r1, tid, 4);
        return;
    }

    const int idx = bid - ZC * BB;
    const int sub = idx % NSUB;
    const int b   = idx / NSUB;
    const int u   = tid;
    __shared__ int sl[32];

    const int A  = g_acnt[b];
    const int i0 = sub * 32;
    const int i1 = min(i0 + 32, A);
    const int n  = max(i1 - i0, 0);

    if (u < 32 && u < n) sl[u] = g_alist[b * VV + i0 + u];
    __syncthreads();

    float acc = 0.0f;
    int i = 0;
    for (; i + 8 <= n; i += 8) {
        float w0 = g_Wt[sl[i + 0] * VV + u];
        float w1 = g_Wt[sl[i + 1] * VV + u];
        float w2 = g_Wt[sl[i + 2] * VV + u];
        float w3 = g_Wt[sl[i + 3] * VV + u];
        float w4 = g_Wt[sl[i + 4] * VV + u];
        float w5 = g_Wt[sl[i + 5] * VV + u];
        float w6 = g_Wt[sl[i + 6] * VV + u];
        float w7 = g_Wt[sl[i + 7] * VV + u];
        acc += ((w0 + w1) + (w2 + w3)) + ((w4 + w5) + (w6 + w7));
    }
    for (; i < n; i++) acc += g_Wt[sl[i] * VV + u];

    g_seg[((size_t)b * NSUB + sub) * VV + u] = acc;
    if (n > 0) atomicAdd(&g_S[b * VV + u], acc);   // accumulate steady row
}

// ---------------------------------------------------------------------------
// Kernel 4 (output), grid (FILLG + NSEG, BB) x 128:  (R7 shape)
//   blockIdx.x <  FILLG : S-fill slice, rows [vend, limit): ONE g_S load
//   blockIdx.x >= FILLG : varying segment s (state = bias + ordered seg prefix)
// ---------------------------------------------------------------------------
__global__ void output_k(const int* __restrict__ lengths, const float* __restrict__ bias,
                         float* __restrict__ out) {
    const int b     = blockIdx.y;
    const int tid   = threadIdx.x;          // float4 lane
    const int limit = lengths[b] - 1;
    const int vend  = min(g_tlast[b], limit);

    float4* obase = (float4*)out + (size_t)b * TM1 * (VV / 4) + tid;

    if (blockIdx.x < FILLG) {
        // ---- S-fill slice over [vend, limit) ----
        const int total = limit - vend;
        if (total <= 0) return;
        const int per = (total + FILLG - 1) / FILLG;
        const int r0  = vend + blockIdx.x * per;
        const int r1  = min(r0 + per, limit);
        if (r0 >= r1) return;

        const float4 S = ((const float4*)(g_S + (size_t)b * VV))[tid];
#pragma unroll 8
        for (int t = r0; t < r1; t++)
            __stcs(&obase[(size_t)t * (VV / 4)], S);
        return;
    }

    // ---- varying segment ----
    if (vend <= 0) return;
    const int s  = blockIdx.x - FILLG;
    const int A  = g_acnt[b];
    const int i0 = s * SEG;
    const int i1 = min(i0 + SEG, A);
    const int n  = max(i1 - i0, 0);
    if (s > 0 && n == 0) return;

    __shared__ int sl[SEG];
    __shared__ int st[SEG];
    __shared__ int s_end;
    if (tid < n) {
        sl[tid] = g_alist[b * VV + i0 + tid];
        st[tid] = g_atime[b * VV + i0 + tid];
    }
    if (tid == 0) s_end = (i1 < A) ? g_atime[b * VV + i1] : vend;
    __syncthreads();

    const int ts = (s == 0) ? 0 : ((n > 0) ? st[0] : vend);
    const int ve = min(s_end, vend);
    if (ts >= ve) return;

    // Starting state = bias + ordered sub-sums [0, 2s)  (deterministic)
    const float4* seg4 = (const float4*)(g_seg + (size_t)b * NSUB * VV);
    float4 L = ((const float4*)bias)[tid];
    for (int q = 0; q < 2 * s; q++) {
        float4 g = seg4[q * (VV / 4) + tid];
        L.x += g.x; L.y += g.y; L.z += g.z; L.w += g.w;
    }

    // Static 8-deep register prefetch over Wt columns
    float4 w[8];
#pragma unroll
    for (int k = 0; k < 8; k++)
        w[k] = (k < n) ? ((const float4*)(g_Wt + (size_t)sl[k] * VV))[tid]
                       : make_float4(0.f, 0.f, 0.f, 0.f);

    int wt = ts;
    for (int base = 0; base < n; base += 8) {
#pragma unroll
        for (int k = 0; k < 8; k++) {
            const int i = base + k;
            if (i < n) {
                const int te = min(st[i], ve);
                while (wt < te) { __stcs(&obase[(size_t)wt * (VV / 4)], L); wt++; }
                L.x += w[k].x; L.y += w[k].y; L.z += w[k].z; L.w += w[k].w;
                const int j = i + 8;
                if (j < n)
                    w[k] = ((const float4*)(g_Wt + (size_t)sl[j] * VV))[tid];
            }
        }
    }
    while (wt < ve) { __stcs(&obase[(size_t)wt * (VV / 4)], L); wt++; }
}

// ---------------------------------------------------------------------------
// Launch. Inputs (metadata order): times[B,T] f32, codes[B,T,V] f32,
// lengths[B] i32, W[V,V] f32, b[V] f32. Output: [B, T-1, V] f32.
// ---------------------------------------------------------------------------
extern "C" void kernel_launch(void* const* d_in, const int* in_sizes, int n_in,
                              void* d_out, int out_size) {
    const float* codes   = (const float*)d_in[1];
    const int*   lengths = (const int*)d_in[2];
    const float* W       = (const float*)d_in[3];
    const float* bias    = (const float*)d_in[4];
    float*       out     = (float*)d_out;

    setup<<<ZA * BB + 256 + 128 + 64, 256>>>(W, codes, lengths, bias, out);
    sort_acts<<<ZB * BB + BB, 512>>>(lengths, out);
    segsum<<<ZC * BB + NSUB * BB, 512>>>(lengths, out);
    output_k<<<dim3(FILLG + NSEG, BB), 128>>>(lengths, bias, out);
}